// round 9
// baseline (speedup 1.0000x reference)
#include <cuda_runtime.h>
#include <math.h>

#define H 8192
#define NSPLIT 64
#define MAX_RPS 128                   // worst case rows per split (fully dense)
#define COLBLKS (H / (256 * 4))       // 8
#define UNROLL 8
#define SGRP 8                         // splits per k3a group

// Scratch (no cudaMalloc allowed)
__device__ float g_h1[H];
__device__ float g_xc[H];                     // compacted nonzero h1 values
__device__ int   g_ic[H];                     // their row indices
__device__ int   g_nnz;
__device__ float g_part[NSPLIT * H];          // layer-2 partials (2 MB, L2)
__device__ float g_part2[(NSPLIT / SGRP) * H];// stage-2 partials (256 KB)
__device__ float g_pen_part[32 * 8];          // head partials
__device__ int   g_done_cnt;                  // k3b completion counter

// ---- k1: h1 = relu(state @ W1 + b1), 32 blocks ----
__global__ void __launch_bounds__(256) k1_layer1(const float* __restrict__ state,
                                                 const float* __restrict__ W1,
                                                 const float* __restrict__ b1) {
    __shared__ float s[42];
    int t = threadIdx.x;
    if (t < 42) s[t] = state[t];
    __syncthreads();
    int j = blockIdx.x * 256 + t;
    float acc = b1[j];
    #pragma unroll
    for (int k = 0; k < 42; k++)
        acc = fmaf(s[k], W1[(size_t)k * H + j], acc);
    g_h1[j] = fmaxf(acc, 0.0f);
}

// ---- k1b: deterministic order-preserving global compaction (1 block) ----
__global__ void __launch_bounds__(1024) k1b_compact() {
    __shared__ int warp_tot[32];
    int t = threadIdx.x;
    int lane = t & 31, wid = t >> 5;

    float v[8];
    int base = t * 8;
    int cnt = 0;
    #pragma unroll
    for (int i = 0; i < 8; i++) {
        v[i] = g_h1[base + i];
        cnt += (v[i] > 0.0f);
    }

    int x = cnt;
    #pragma unroll
    for (int d = 1; d < 32; d <<= 1) {
        int y = __shfl_up_sync(0xFFFFFFFF, x, d);
        if (lane >= d) x += y;
    }
    if (lane == 31) warp_tot[wid] = x;
    int excl = x - cnt;
    __syncthreads();
    if (wid == 0) {
        int w = warp_tot[lane];
        #pragma unroll
        for (int d = 1; d < 32; d <<= 1) {
            int y = __shfl_up_sync(0xFFFFFFFF, w, d);
            if (lane >= d) w += y;
        }
        warp_tot[lane] = w;
    }
    __syncthreads();
    int offset = excl + (wid > 0 ? warp_tot[wid - 1] : 0);

    #pragma unroll
    for (int i = 0; i < 8; i++) {
        if (v[i] > 0.0f) {
            g_xc[offset] = v[i];
            g_ic[offset] = base + i;
            offset++;
        }
    }
    if (t == 1023) g_nnz = offset;
}

// ---- k2: balanced sparse split-K GEMV (each split gets exactly ~nnz/64 rows) ----
__global__ void __launch_bounds__(256, 4) k2_sparse(const float* __restrict__ W2) {
    __shared__ float xs[MAX_RPS];
    __shared__ int   ridx[MAX_RPS];
    int t = threadIdx.x;

    int nnz = g_nnz;
    int rps = (nnz + NSPLIT - 1) / NSPLIT;
    int rbeg = blockIdx.y * rps;
    int rend = min(rbeg + rps, nnz);
    int nr = rend - rbeg; if (nr < 0) nr = 0;

    if (t < nr) {
        xs[t]   = g_xc[rbeg + t];
        ridx[t] = g_ic[rbeg + t];
    }
    __syncthreads();

    int c = (blockIdx.x * 256 + t) * 4;
    float4 acc = make_float4(0.f, 0.f, 0.f, 0.f);

    int nr8 = nr & ~(UNROLL - 1);
    for (int rb = 0; rb < nr8; rb += UNROLL) {
        float4 w[UNROLL];
        #pragma unroll
        for (int u = 0; u < UNROLL; u++)
            w[u] = __ldcs(reinterpret_cast<const float4*>(
                       W2 + (size_t)ridx[rb + u] * H + c));
        #pragma unroll
        for (int u = 0; u < UNROLL; u++) {
            float xv = xs[rb + u];
            acc.x = fmaf(xv, w[u].x, acc.x);
            acc.y = fmaf(xv, w[u].y, acc.y);
            acc.z = fmaf(xv, w[u].z, acc.z);
            acc.w = fmaf(xv, w[u].w, acc.w);
        }
    }
    for (int r = nr8; r < nr; r++) {
        float4 w = __ldcs(reinterpret_cast<const float4*>(
                       W2 + (size_t)ridx[r] * H + c));
        float xv = xs[r];
        acc.x = fmaf(xv, w.x, acc.x);
        acc.y = fmaf(xv, w.y, acc.y);
        acc.z = fmaf(xv, w.z, acc.z);
        acc.w = fmaf(xv, w.w, acc.w);
    }
    *reinterpret_cast<float4*>(g_part + (size_t)blockIdx.y * H + c) = acc;
}

// ---- k3a: stage-1 reduce — 256 blocks, each sums SGRP=8 partials for 256 cols ----
__global__ void __launch_bounds__(256) k3a(void) {
    int t = threadIdx.x;
    int j = blockIdx.x * 256 + t;
    int g = blockIdx.y;
    float a[SGRP];
    #pragma unroll
    for (int sIdx = 0; sIdx < SGRP; sIdx++)
        a[sIdx] = g_part[(size_t)(g * SGRP + sIdx) * H + j];
    float acc = 0.0f;
    #pragma unroll
    for (int sIdx = 0; sIdx < SGRP; sIdx++) acc += a[sIdx];
    g_part2[(size_t)g * H + j] = acc;
}

// ---- k3b: stage-2 reduce + relu + W3 head + last-arriver softmax ----
__global__ void __launch_bounds__(256) k3b(const float* __restrict__ state,
                                           const float* __restrict__ b2,
                                           const float* __restrict__ W3,
                                           const float* __restrict__ b3,
                                           float* __restrict__ out) {
    __shared__ float red[256][8];
    __shared__ int   flag;
    int t = threadIdx.x;
    int j = blockIdx.x * 256 + t;

    float acc = b2[j];
    #pragma unroll
    for (int g = 0; g < NSPLIT / SGRP; g++)
        acc += g_part2[(size_t)g * H + j];
    float h2 = fmaxf(acc, 0.0f);

    float4 w0 = *reinterpret_cast<const float4*>(W3 + (size_t)j * 8);
    float4 w1 = *reinterpret_cast<const float4*>(W3 + (size_t)j * 8 + 4);
    red[t][0] = h2 * w0.x;  red[t][1] = h2 * w0.y;
    red[t][2] = h2 * w0.z;  red[t][3] = h2 * w0.w;
    red[t][4] = h2 * w1.x;  red[t][5] = h2 * w1.y;
    red[t][6] = h2 * w1.z;  red[t][7] = h2 * w1.w;
    __syncthreads();

    for (int stride = 128; stride > 0; stride >>= 1) {
        if (t < stride) {
            #pragma unroll
            for (int n = 0; n < 8; n++) red[t][n] += red[t + stride][n];
        }
        __syncthreads();
    }
    if (t < 8) g_pen_part[blockIdx.x * 8 + t] = red[0][t];

    __syncthreads();
    __threadfence();
    if (t == 0) {
        int old = atomicAdd(&g_done_cnt, 1);
        flag = (old == 31);
        if (flag) g_done_cnt = 0;   // reset for graph replay
    }
    __syncthreads();
    if (!flag) return;
    __threadfence();

    if (t == 0) {
        float pens[8];
        #pragma unroll
        for (int n = 0; n < 8; n++) {
            float a = b3[n];
            #pragma unroll
            for (int b = 0; b < 32; b++)
                a += g_pen_part[b * 8 + n];
            pens[n] = a;
        }
        float value = pens[7];
        bool legal[7];
        float mx = -INFINITY;
        #pragma unroll
        for (int n = 0; n < 7; n++) {
            legal[n] = (state[n] == 0.0f);
            if (legal[n] && pens[n] > mx) mx = pens[n];
        }
        float e[7];
        float sum = 0.0f;
        #pragma unroll
        for (int n = 0; n < 7; n++) {
            e[n] = legal[n] ? expf(pens[n] - mx) : 0.0f;
            sum += e[n];
        }
        float inv = 1.0f / sum;
        out[0] = value;
        #pragma unroll
        for (int n = 0; n < 7; n++) out[1 + n] = e[n] * inv;
    }
}

extern "C" void kernel_launch(void* const* d_in, const int* in_sizes, int n_in,
                              void* d_out, int out_size) {
    const float* state = (const float*)d_in[0];
    const float* W1    = (const float*)d_in[1];
    const float* b1    = (const float*)d_in[2];
    const float* W2    = (const float*)d_in[3];
    const float* b2    = (const float*)d_in[4];
    const float* W3    = (const float*)d_in[5];
    const float* b3    = (const float*)d_in[6];
    float* out = (float*)d_out;

    k1_layer1<<<H / 256, 256>>>(state, W1, b1);
    k1b_compact<<<1, 1024>>>();

    dim3 g2(COLBLKS, NSPLIT);             // (8, 64) = 512 blocks, perfectly balanced
    k2_sparse<<<g2, 256>>>(W2);

    dim3 g3(32, NSPLIT / SGRP);           // (32, 8) = 256 blocks
    k3a<<<g3, 256>>>();

    k3b<<<32, 256>>>(state, b2, W3, b3, out);
}

// round 10
// speedup vs baseline: 1.4303x; 1.4303x over previous
#include <cuda_runtime.h>
#include <math.h>

#define H 8192
#define NSPLIT 64
#define ROWS_PER_SPLIT (H / NSPLIT)   // 128
#define COLBLKS (H / (256 * 4))       // 8
#define UNROLL 8
#define SGRP 8                         // splits per k3a group
#define CACHE_LIM 84                   // local row idx < 84 -> L2-cached loads (~88 MB resident)

// Scratch (no cudaMalloc allowed)
__device__ float g_part[NSPLIT * H];          // layer-2 partials (2 MB, L2)
__device__ float g_part2[(NSPLIT / SGRP) * H];// stage-2 partials (256 KB)
__device__ float g_pen_part[32 * 8];          // head partials
__device__ int   g_done_cnt;                  // k3b completion counter

// ---- k2: fused h1-recompute + two-list compaction (cached / streamed) + GEMV ----
__global__ void __launch_bounds__(256, 4) k2_fused(const float* __restrict__ state,
                                                   const float* __restrict__ W1,
                                                   const float* __restrict__ b1,
                                                   const float* __restrict__ W2) {
    __shared__ float s[42];
    __shared__ float xs[ROWS_PER_SPLIT];
    __shared__ int   ridx[ROWS_PER_SPLIT];
    __shared__ int   c1[4], c2[4];
    int t = threadIdx.x;
    int lane = t & 31, wid = t >> 5;
    if (t < 42) s[t] = state[t];
    __syncthreads();

    int r0 = blockIdx.y * ROWS_PER_SPLIT;

    // compute h1 slice; classify nonzero rows into cached (t<CACHE_LIM) / streamed
    float v = 0.0f;
    bool cach = false, strm = false;
    if (t < ROWS_PER_SPLIT) {
        float acc = b1[r0 + t];
        #pragma unroll
        for (int k = 0; k < 42; k++)
            acc = fmaf(s[k], __ldg(W1 + (size_t)k * H + r0 + t), acc);
        v = fmaxf(acc, 0.0f);
        cach = (v > 0.0f) && (t <  CACHE_LIM);
        strm = (v > 0.0f) && (t >= CACHE_LIM);
    }
    unsigned m1 = __ballot_sync(0xFFFFFFFF, cach);
    unsigned m2 = __ballot_sync(0xFFFFFFFF, strm);
    if (lane == 0 && wid < 4) { c1[wid] = __popc(m1); c2[wid] = __popc(m2); }
    __syncthreads();
    int nc = c1[0] + c1[1] + c1[2] + c1[3];
    int ns = c2[0] + c2[1] + c2[2] + c2[3];
    unsigned lt = (1u << lane) - 1;
    if (cach) {
        int off = __popc(m1 & lt);
        for (int w = 0; w < 4; w++) if (w < wid) off += c1[w];
        xs[off] = v;  ridx[off] = r0 + t;
    }
    if (strm) {
        int off = nc + __popc(m2 & lt);
        for (int w = 0; w < 4; w++) if (w < wid) off += c2[w];
        xs[off] = v;  ridx[off] = r0 + t;
    }
    __syncthreads();

    int c = (blockIdx.x * 256 + t) * 4;
    float4 acc = make_float4(0.f, 0.f, 0.f, 0.f);

    // ---- cached list: default caching -> L2-resident across graph replays ----
    int nc8 = nc & ~(UNROLL - 1);
    for (int rb = 0; rb < nc8; rb += UNROLL) {
        float4 w[UNROLL];
        #pragma unroll
        for (int u = 0; u < UNROLL; u++)
            w[u] = __ldg(reinterpret_cast<const float4*>(
                       W2 + (size_t)ridx[rb + u] * H + c));
        #pragma unroll
        for (int u = 0; u < UNROLL; u++) {
            float xv = xs[rb + u];
            acc.x = fmaf(xv, w[u].x, acc.x);
            acc.y = fmaf(xv, w[u].y, acc.y);
            acc.z = fmaf(xv, w[u].z, acc.z);
            acc.w = fmaf(xv, w[u].w, acc.w);
        }
    }
    for (int r = nc8; r < nc; r++) {
        float4 w = __ldg(reinterpret_cast<const float4*>(
                       W2 + (size_t)ridx[r] * H + c));
        float xv = xs[r];
        acc.x = fmaf(xv, w.x, acc.x);  acc.y = fmaf(xv, w.y, acc.y);
        acc.z = fmaf(xv, w.z, acc.z);  acc.w = fmaf(xv, w.w, acc.w);
    }

    // ---- streamed list: evict-first, never displaces the resident set ----
    int ne = nc + ns;
    int ns8 = nc + ((ne - nc) & ~(UNROLL - 1));
    for (int rb = nc; rb < ns8; rb += UNROLL) {
        float4 w[UNROLL];
        #pragma unroll
        for (int u = 0; u < UNROLL; u++)
            w[u] = __ldcs(reinterpret_cast<const float4*>(
                       W2 + (size_t)ridx[rb + u] * H + c));
        #pragma unroll
        for (int u = 0; u < UNROLL; u++) {
            float xv = xs[rb + u];
            acc.x = fmaf(xv, w[u].x, acc.x);
            acc.y = fmaf(xv, w[u].y, acc.y);
            acc.z = fmaf(xv, w[u].z, acc.z);
            acc.w = fmaf(xv, w[u].w, acc.w);
        }
    }
    for (int r = ns8; r < ne; r++) {
        float4 w = __ldcs(reinterpret_cast<const float4*>(
                       W2 + (size_t)ridx[r] * H + c));
        float xv = xs[r];
        acc.x = fmaf(xv, w.x, acc.x);  acc.y = fmaf(xv, w.y, acc.y);
        acc.z = fmaf(xv, w.z, acc.z);  acc.w = fmaf(xv, w.w, acc.w);
    }

    *reinterpret_cast<float4*>(g_part + (size_t)blockIdx.y * H + c) = acc;
}

// ---- k3a: stage-1 reduce — 256 blocks, each sums SGRP=8 partials for 256 cols ----
__global__ void __launch_bounds__(256) k3a(void) {
    int t = threadIdx.x;
    int j = blockIdx.x * 256 + t;
    int g = blockIdx.y;
    float a[SGRP];
    #pragma unroll
    for (int sIdx = 0; sIdx < SGRP; sIdx++)
        a[sIdx] = g_part[(size_t)(g * SGRP + sIdx) * H + j];
    float acc = 0.0f;
    #pragma unroll
    for (int sIdx = 0; sIdx < SGRP; sIdx++) acc += a[sIdx];
    g_part2[(size_t)g * H + j] = acc;
}

// ---- k3b: stage-2 reduce + relu + W3 head + last-arriver softmax ----
__global__ void __launch_bounds__(256) k3b(const float* __restrict__ state,
                                           const float* __restrict__ b2,
                                           const float* __restrict__ W3,
                                           const float* __restrict__ b3,
                                           float* __restrict__ out) {
    __shared__ float red[256][8];
    __shared__ int   flag;
    int t = threadIdx.x;
    int j = blockIdx.x * 256 + t;

    float acc = b2[j];
    #pragma unroll
    for (int g = 0; g < NSPLIT / SGRP; g++)
        acc += g_part2[(size_t)g * H + j];
    float h2 = fmaxf(acc, 0.0f);

    float4 w0 = *reinterpret_cast<const float4*>(W3 + (size_t)j * 8);
    float4 w1 = *reinterpret_cast<const float4*>(W3 + (size_t)j * 8 + 4);
    red[t][0] = h2 * w0.x;  red[t][1] = h2 * w0.y;
    red[t][2] = h2 * w0.z;  red[t][3] = h2 * w0.w;
    red[t][4] = h2 * w1.x;  red[t][5] = h2 * w1.y;
    red[t][6] = h2 * w1.z;  red[t][7] = h2 * w1.w;
    __syncthreads();

    for (int stride = 128; stride > 0; stride >>= 1) {
        if (t < stride) {
            #pragma unroll
            for (int n = 0; n < 8; n++) red[t][n] += red[t + stride][n];
        }
        __syncthreads();
    }
    if (t < 8) g_pen_part[blockIdx.x * 8 + t] = red[0][t];

    __syncthreads();
    __threadfence();
    if (t == 0) {
        int old = atomicAdd(&g_done_cnt, 1);
        flag = (old == 31);
        if (flag) g_done_cnt = 0;   // reset for graph replay
    }
    __syncthreads();
    if (!flag) return;
    __threadfence();

    if (t == 0) {
        float pens[8];
        #pragma unroll
        for (int n = 0; n < 8; n++) {
            float a = b3[n];
            #pragma unroll
            for (int b = 0; b < 32; b++)
                a += g_pen_part[b * 8 + n];
            pens[n] = a;
        }
        float value = pens[7];
        bool legal[7];
        float mx = -INFINITY;
        #pragma unroll
        for (int n = 0; n < 7; n++) {
            legal[n] = (state[n] == 0.0f);
            if (legal[n] && pens[n] > mx) mx = pens[n];
        }
        float e[7];
        float sum = 0.0f;
        #pragma unroll
        for (int n = 0; n < 7; n++) {
            e[n] = legal[n] ? expf(pens[n] - mx) : 0.0f;
            sum += e[n];
        }
        float inv = 1.0f / sum;
        out[0] = value;
        #pragma unroll
        for (int n = 0; n < 7; n++) out[1 + n] = e[n] * inv;
    }
}

extern "C" void kernel_launch(void* const* d_in, const int* in_sizes, int n_in,
                              void* d_out, int out_size) {
    const float* state = (const float*)d_in[0];
    const float* W1    = (const float*)d_in[1];
    const float* b1    = (const float*)d_in[2];
    const float* W2    = (const float*)d_in[3];
    const float* b2    = (const float*)d_in[4];
    const float* W3    = (const float*)d_in[5];
    const float* b3    = (const float*)d_in[6];
    float* out = (float*)d_out;

    dim3 g2(COLBLKS, NSPLIT);             // (8, 64) = 512 blocks
    k2_fused<<<g2, 256>>>(state, W1, b1, W2);

    dim3 g3(32, NSPLIT / SGRP);           // (32, 8) = 256 blocks
    k3a<<<g3, 256>>>();

    k3b<<<32, 256>>>(state, b2, W3, b3, out);
}